// round 1
// baseline (speedup 1.0000x reference)
#include <cuda_runtime.h>

#define DL 64
#define D 65                 // DL + 1
#define NIJ (D * D)          // 4225
#define HID 64
#define B_TOTAL 512
#define MTILE 256
#define M_TILES 2            // 512 / 256
#define SPLITS 74            // 2 * 74 = 148 CTAs = 1 full wave
#define NTHREADS 256
#define TSS (MTILE + 8)      // 264: padded stride for transposed t tile
#define WSS 68               // padded stride for W block rows

// K-split partial accumulators: [SPLITS][B_TOTAL][HID] = 9.7 MB
__device__ float g_partial[SPLITS * B_TOTAL * HID];

// SMEM layout (dynamic): Ts [D][TSS], Ws [D][WSS], AVs [MTILE]
#define SMEM_FLOATS (D * TSS + D * WSS + MTILE)

__global__ void __launch_bounds__(NTHREADS, 1)
fusion_gemm_kernel(const float* __restrict__ l,
                   const float* __restrict__ a,
                   const float* __restrict__ v,
                   const float* __restrict__ W1)
{
    extern __shared__ float smem[];
    float* Ts  = smem;                 // [D][TSS]  t_h transposed: Ts[k*TSS + b]
    float* Ws  = smem + D * TSS;       // [D][WSS]  W block: Ws[k*WSS + n]
    float* AVs = Ws + D * WSS;         // [MTILE]   a_h[b,i]*v_h[b,j] for current ij

    const int tid = threadIdx.x;
    const int mt  = blockIdx.x;        // 0..M_TILES-1
    const int s   = blockIdx.y;        // 0..SPLITS-1
    const int b0  = mt * MTILE;

    // ---- Build transposed t_h tile: Ts[k][b] = (k==0 ? 1 : l[b0+b][k-1]) ----
    Ts[tid] = 1.0f;  // k = 0 row, b = tid (MTILE == NTHREADS)
    {
        const float4* lg = (const float4*)(l + (size_t)b0 * DL);
        #pragma unroll
        for (int it = 0; it < (MTILE * DL / 4) / NTHREADS; it++) {
            int idx = it * NTHREADS + tid;       // float4 index
            float4 val = lg[idx];
            int b = (idx * 4) >> 6;              // / DL
            int k = (idx * 4) & 63;              // % DL
            Ts[(k + 1) * TSS + b] = val.x;
            Ts[(k + 2) * TSS + b] = val.y;
            Ts[(k + 3) * TSS + b] = val.z;
            Ts[(k + 4) * TSS + b] = val.w;
        }
    }

    const int tx = tid & 7;            // n-group (8 groups of 8 cols)
    const int ty = tid >> 3;           // b-group (32 groups of 8 rows)
    const int row0 = ty * 8;
    const int col0 = tx * 8;

    // ij range for this split
    const int per = NIJ / SPLITS;      // 57
    const int rem = NIJ % SPLITS;      // 7
    const int ij0 = s * per + (s < rem ? s : rem);
    const int cnt = per + (s < rem ? 1 : 0);

    float acc[8][8];
    #pragma unroll
    for (int u = 0; u < 8; u++)
        #pragma unroll
        for (int w = 0; w < 8; w++) acc[u][w] = 0.0f;

    for (int t = 0; t < cnt; t++) {
        const int ij = ij0 + t;
        __syncthreads();  // protect Ws/AVs reuse (and covers Ts build at t=0)

        // ---- Load W block: 65x64 contiguous floats at W1 + ij*4160 ----
        {
            const float4* wg = (const float4*)(W1 + (size_t)ij * (D * HID));
            #pragma unroll
            for (int it = 0; it < 5; it++) {
                int f = it * NTHREADS + tid;
                if (f < (D * HID) / 4) {
                    float4 val = wg[f];
                    int k = (f * 4) >> 6;
                    int n = (f * 4) & 63;
                    *(float4*)&Ws[k * WSS + n] = val;
                }
            }
        }
        // ---- av[b] = a_h[b,i] * v_h[b,j] for this ij (one value per thread) ----
        {
            int i = ij / D;
            int j = ij - i * D;
            int b = b0 + tid;
            float ai = (i == 0) ? 1.0f : __ldg(&a[(size_t)b * DL + (i - 1)]);
            float vj = (j == 0) ? 1.0f : __ldg(&v[(size_t)b * DL + (j - 1)]);
            AVs[tid] = ai * vj;
        }
        __syncthreads();

        // ---- inner = T_tile[8b x 65] @ W_block[65 x 8n] ----
        float inner[8][8];
        #pragma unroll
        for (int u = 0; u < 8; u++)
            #pragma unroll
            for (int w = 0; w < 8; w++) inner[u][w] = 0.0f;

        #pragma unroll 5
        for (int k = 0; k < D; k++) {
            float4 t0 = *(const float4*)&Ts[k * TSS + row0];
            float4 t1 = *(const float4*)&Ts[k * TSS + row0 + 4];
            float4 w0 = *(const float4*)&Ws[k * WSS + col0];
            float4 w1 = *(const float4*)&Ws[k * WSS + col0 + 4];
            float tr[8] = {t0.x, t0.y, t0.z, t0.w, t1.x, t1.y, t1.z, t1.w};
            float wr[8] = {w0.x, w0.y, w0.z, w0.w, w1.x, w1.y, w1.z, w1.w};
            #pragma unroll
            for (int u = 0; u < 8; u++)
                #pragma unroll
                for (int w = 0; w < 8; w++)
                    inner[u][w] = fmaf(tr[u], wr[w], inner[u][w]);
        }

        // ---- acc += av[b] * inner  (fold rank-1 scale, 1.5% overhead) ----
        float avr[8];
        {
            float4 av0 = *(const float4*)&AVs[row0];
            float4 av1 = *(const float4*)&AVs[row0 + 4];
            avr[0] = av0.x; avr[1] = av0.y; avr[2] = av0.z; avr[3] = av0.w;
            avr[4] = av1.x; avr[5] = av1.y; avr[6] = av1.z; avr[7] = av1.w;
        }
        #pragma unroll
        for (int u = 0; u < 8; u++)
            #pragma unroll
            for (int w = 0; w < 8; w++)
                acc[u][w] = fmaf(avr[u], inner[u][w], acc[u][w]);
    }

    // ---- Write partial [256 x 64] for this (split, mtile) ----
    float* outp = g_partial + ((size_t)s * B_TOTAL + b0 + row0) * HID + col0;
    #pragma unroll
    for (int u = 0; u < 8; u++) {
        *(float4*)(outp + (size_t)u * HID)
            = make_float4(acc[u][0], acc[u][1], acc[u][2], acc[u][3]);
        *(float4*)(outp + (size_t)u * HID + 4)
            = make_float4(acc[u][4], acc[u][5], acc[u][6], acc[u][7]);
    }
}

// Reduce K-split partials + tanh + layer2 + tanh + layer3 + tanh
__global__ void epilogue_kernel(const float* __restrict__ b1,
                                const float* __restrict__ W2,
                                const float* __restrict__ b2,
                                const float* __restrict__ W3,
                                const float* __restrict__ b3,
                                float* __restrict__ out)
{
    __shared__ float h1s[HID];
    __shared__ float h2s[HID];
    const int b = blockIdx.x;    // 0..511
    const int n = threadIdx.x;   // 0..63

    float s1 = b1[n];
    const float* p = g_partial + (size_t)b * HID + n;
    #pragma unroll
    for (int s = 0; s < SPLITS; s++)
        s1 += p[(size_t)s * B_TOTAL * HID];
    h1s[n] = tanhf(s1);
    __syncthreads();

    float s2 = b2[n];
    #pragma unroll
    for (int m = 0; m < HID; m++)
        s2 = fmaf(h1s[m], W2[m * HID + n], s2);
    h2s[n] = tanhf(s2);
    __syncthreads();

    float s3 = b3[n];
    #pragma unroll
    for (int m = 0; m < HID; m++)
        s3 = fmaf(h2s[m], W3[m * HID + n], s3);
    out[(size_t)b * HID + n] = tanhf(s3);
}

extern "C" void kernel_launch(void* const* d_in, const int* in_sizes, int n_in,
                              void* d_out, int out_size)
{
    const float* l  = (const float*)d_in[0];
    const float* a  = (const float*)d_in[1];
    const float* v  = (const float*)d_in[2];
    const float* W1 = (const float*)d_in[3];
    const float* b1 = (const float*)d_in[4];
    const float* W2 = (const float*)d_in[5];
    const float* b2 = (const float*)d_in[6];
    const float* W3 = (const float*)d_in[7];
    const float* b3 = (const float*)d_in[8];
    float* out = (float*)d_out;

    const int smem_bytes = SMEM_FLOATS * (int)sizeof(float);  // ~87.3 KB
    cudaFuncSetAttribute(fusion_gemm_kernel,
                         cudaFuncAttributeMaxDynamicSharedMemorySize, smem_bytes);

    dim3 grid(M_TILES, SPLITS);
    fusion_gemm_kernel<<<grid, NTHREADS, smem_bytes>>>(l, a, v, W1);
    epilogue_kernel<<<B_TOTAL, HID>>>(b1, W2, b2, W3, b3, out);
}